// round 2
// baseline (speedup 1.0000x reference)
#include <cuda_runtime.h>
#include <math.h>

#define B_  4
#define S_  4096
#define D_  1024
#define H_  16
#define R_  256
#define DK_ 64
#define M_  (B_*S_)   // 16384 rows for the big GEMMs

// ---------------- scratch (device globals; no allocation allowed) ----------------
__device__ float g_q [B_*S_*D_];        // 64 MB
__device__ float g_k [B_*S_*D_];
__device__ float g_v [B_*S_*D_];
__device__ float g_ao[B_*S_*D_];        // attention output pre-Wo
__device__ float g_kp[B_*H_*DK_*R_];    // 16 MB
__device__ float g_vp[B_*H_*DK_*R_];

// ============================================================================
// Generic NT SGEMM:  C[M,N] = A[M,K] @ W[N,K]^T + bias[N]
// M=16384, N=K=1024.  128x128 tile, BK=16, 256 threads, 8x8 per thread.
// csel: 0->g_q, 1->g_k, 2->g_v, 3->Cext.  Aext==nullptr -> g_ao.
// ============================================================================
__global__ __launch_bounds__(256) void gemm_nt(const float* __restrict__ Aext,
                                               const float* __restrict__ W,
                                               const float* __restrict__ bias,
                                               float* Cext, int csel)
{
    const int K = D_;
    const int N = D_;
    const float* A = Aext ? Aext : g_ao;
    float* C = (csel == 0) ? g_q : (csel == 1) ? g_k : (csel == 2) ? g_v : Cext;

    __shared__ float As[16][132];   // [k][m]  (pad 132 to break store-phase conflicts)
    __shared__ float Bs[16][132];   // [k][n]

    const int tid = threadIdx.x;
    const int m0 = blockIdx.y * 128;
    const int n0 = blockIdx.x * 128;
    const int tx = tid & 15;        // n-group
    const int ty = tid >> 4;        // m-group

    float acc[8][8];
    #pragma unroll
    for (int i = 0; i < 8; i++)
        #pragma unroll
        for (int j = 0; j < 8; j++) acc[i][j] = 0.f;

    for (int k0 = 0; k0 < K; k0 += 16) {
        // load A tile (128x16) and W tile (128x16); both row-major stride K
        #pragma unroll
        for (int u = 0; u < 2; u++) {
            int f   = tid + u * 256;     // 0..511  (512 float4 per tile)
            int row = f >> 2;            // 0..127
            int c4  = (f & 3) * 4;       // 0,4,8,12
            float4 av = *(const float4*)(A + (size_t)(m0 + row) * K + k0 + c4);
            As[c4 + 0][row] = av.x; As[c4 + 1][row] = av.y;
            As[c4 + 2][row] = av.z; As[c4 + 3][row] = av.w;
            float4 wv = *(const float4*)(W + (size_t)(n0 + row) * K + k0 + c4);
            Bs[c4 + 0][row] = wv.x; Bs[c4 + 1][row] = wv.y;
            Bs[c4 + 2][row] = wv.z; Bs[c4 + 3][row] = wv.w;
        }
        __syncthreads();
        #pragma unroll
        for (int kk = 0; kk < 16; kk++) {
            float ra[8], rb[8];
            *(float4*)&ra[0] = *(const float4*)&As[kk][ty * 8];
            *(float4*)&ra[4] = *(const float4*)&As[kk][ty * 8 + 4];
            *(float4*)&rb[0] = *(const float4*)&Bs[kk][tx * 8];
            *(float4*)&rb[4] = *(const float4*)&Bs[kk][tx * 8 + 4];
            #pragma unroll
            for (int i = 0; i < 8; i++)
                #pragma unroll
                for (int j = 0; j < 8; j++)
                    acc[i][j] = fmaf(ra[i], rb[j], acc[i][j]);
        }
        __syncthreads();
    }

    float bb[8];
    #pragma unroll
    for (int j = 0; j < 8; j++) bb[j] = bias[n0 + tx * 8 + j];

    #pragma unroll
    for (int i = 0; i < 8; i++) {
        const size_t m = m0 + ty * 8 + i;
        float* cp = C + m * N + n0 + tx * 8;
        *(float4*)(cp + 0) = make_float4(acc[i][0] + bb[0], acc[i][1] + bb[1],
                                         acc[i][2] + bb[2], acc[i][3] + bb[3]);
        *(float4*)(cp + 4) = make_float4(acc[i][4] + bb[4], acc[i][5] + bb[5],
                                         acc[i][6] + bb[6], acc[i][7] + bb[7]);
    }
}

// ============================================================================
// kp[b,h,d,r] = sum_s k[b,s,h*64+d] * E[h,s,r]    (and vp from v,F)
// Per block: one (b,h), 64(d) x 128(r) tile, K=S=4096, BK=32.
// 256 threads, each 4x8.
// grid: (R/128=2, 1, 128)  z = which*64 + bh
// ============================================================================
__global__ __launch_bounds__(256) void proj_kernel(const float* __restrict__ E,
                                                   const float* __restrict__ F)
{
    const int z     = blockIdx.z;
    const int which = z >> 6;          // 0: kp, 1: vp
    const int bh    = z & 63;
    const int b     = bh >> 4, h = bh & 15;
    const float* Kin  = which ? g_v : g_k;
    const float* Ein  = which ? F : E;
    float*       Cout = which ? g_vp : g_kp;

    __shared__ float As[32][64];    // [s][d]
    __shared__ float Bs[32][128];   // [s][r]

    const int tid = threadIdx.x;
    const int r0  = blockIdx.x * 128;
    const int tx  = tid & 15;       // r-group (8 wide)
    const int ty  = tid >> 4;       // d-group (4 wide), 0..15

    float acc[4][8];
    #pragma unroll
    for (int i = 0; i < 4; i++)
        #pragma unroll
        for (int j = 0; j < 8; j++) acc[i][j] = 0.f;

    const float* Abase = Kin + (size_t)b * S_ * D_ + h * DK_;     // [s][d] stride D_
    const float* Bbase = Ein + (size_t)h * S_ * R_ + r0;          // [s][r] stride R_

    for (int s0 = 0; s0 < S_; s0 += 32) {
        #pragma unroll
        for (int u = 0; u < 2; u++) {            // A: 32x64 = 512 float4
            int f   = tid + u * 256;
            int row = f >> 4;                    // 0..31
            int c4  = (f & 15) * 4;
            *(float4*)&As[row][c4] =
                *(const float4*)(Abase + (size_t)(s0 + row) * D_ + c4);
        }
        #pragma unroll
        for (int u = 0; u < 4; u++) {            // B: 32x128 = 1024 float4
            int f   = tid + u * 256;
            int row = f >> 5;                    // 0..31
            int c4  = (f & 31) * 4;
            *(float4*)&Bs[row][c4] =
                *(const float4*)(Bbase + (size_t)(s0 + row) * R_ + c4);
        }
        __syncthreads();
        #pragma unroll
        for (int kk = 0; kk < 32; kk++) {
            float ra[4], rb[8];
            *(float4*)&ra[0] = *(const float4*)&As[kk][ty * 4];
            *(float4*)&rb[0] = *(const float4*)&Bs[kk][tx * 8];
            *(float4*)&rb[4] = *(const float4*)&Bs[kk][tx * 8 + 4];
            #pragma unroll
            for (int i = 0; i < 4; i++)
                #pragma unroll
                for (int j = 0; j < 8; j++)
                    acc[i][j] = fmaf(ra[i], rb[j], acc[i][j]);
        }
        __syncthreads();
    }

    float* Cb = Cout + (size_t)bh * DK_ * R_ + r0;
    #pragma unroll
    for (int i = 0; i < 4; i++) {
        const int d = ty * 4 + i;
        *(float4*)(Cb + (size_t)d * R_ + tx * 8) =
            make_float4(acc[i][0], acc[i][1], acc[i][2], acc[i][3]);
        *(float4*)(Cb + (size_t)d * R_ + tx * 8 + 4) =
            make_float4(acc[i][4], acc[i][5], acc[i][6], acc[i][7]);
    }
}

// ============================================================================
// Fused attention: per (b,h, 16-row s-tile):
//   scores[16,256] = (q/8) @ kp ; softmax over r; out[16,64] = p @ vp^T
// grid: (S/16=256, B*H=64), 256 threads.
// ============================================================================
__global__ __launch_bounds__(256) void attn_kernel()
{
    const int bh = blockIdx.y;
    const int b  = bh >> 4, h = bh & 15;
    const int s0 = blockIdx.x * 16;
    const int tid = threadIdx.x;

    __shared__ float qs[16][64];        // q tile, pre-scaled by 1/8
    __shared__ float sc[16][256];       // softmax probabilities
    __shared__ float buf[64 * 65];      // reused: kp chunk [16][256] then vp chunk [64][65]

    // ---- load q tile (scaled) ----
    {
        int row = tid >> 4;             // 0..15
        int c4  = (tid & 15) * 4;
        float4 v = *(const float4*)(g_q + (size_t)(b * S_ + s0 + row) * D_ + h * DK_ + c4);
        qs[row][c4 + 0] = v.x * 0.125f; qs[row][c4 + 1] = v.y * 0.125f;
        qs[row][c4 + 2] = v.z * 0.125f; qs[row][c4 + 3] = v.w * 0.125f;
    }

    // ---- phase A: scores ----
    // warp w handles rows w and w+8; lane l handles r = l + j*32, j<8
    const int lane = tid & 31;
    const int w    = tid >> 5;          // 0..7
    float acc_a[8], acc_b[8];
    #pragma unroll
    for (int j = 0; j < 8; j++) { acc_a[j] = 0.f; acc_b[j] = 0.f; }

    const float* kpb = g_kp + (size_t)bh * DK_ * R_;
    for (int dc = 0; dc < DK_; dc += 16) {
        // load kp chunk [16 d][256 r] into buf (4096 floats)
        #pragma unroll
        for (int u = 0; u < 4; u++) {
            int f   = tid + u * 256;
            int row = f >> 6;           // 0..15
            int c4  = (f & 63) * 4;
            *(float4*)&buf[row * 256 + c4] =
                *(const float4*)(kpb + (size_t)(dc + row) * R_ + c4);
        }
        __syncthreads();
        #pragma unroll
        for (int dd = 0; dd < 16; dd++) {
            const float qa = qs[w][dc + dd];
            const float qb = qs[w + 8][dc + dd];
            #pragma unroll
            for (int j = 0; j < 8; j++) {
                const float bv = buf[dd * 256 + lane + j * 32];
                acc_a[j] = fmaf(qa, bv, acc_a[j]);
                acc_b[j] = fmaf(qb, bv, acc_b[j]);
            }
        }
        __syncthreads();
    }

    // ---- softmax over r (256 values spread across 32 lanes x 8 regs) ----
    {
        float mxa = -1e30f, mxb = -1e30f;
        #pragma unroll
        for (int j = 0; j < 8; j++) { mxa = fmaxf(mxa, acc_a[j]); mxb = fmaxf(mxb, acc_b[j]); }
        #pragma unroll
        for (int o = 16; o > 0; o >>= 1) {
            mxa = fmaxf(mxa, __shfl_xor_sync(0xffffffffu, mxa, o));
            mxb = fmaxf(mxb, __shfl_xor_sync(0xffffffffu, mxb, o));
        }
        float sa = 0.f, sb = 0.f;
        #pragma unroll
        for (int j = 0; j < 8; j++) {
            acc_a[j] = __expf(acc_a[j] - mxa); sa += acc_a[j];
            acc_b[j] = __expf(acc_b[j] - mxb); sb += acc_b[j];
        }
        #pragma unroll
        for (int o = 16; o > 0; o >>= 1) {
            sa += __shfl_xor_sync(0xffffffffu, sa, o);
            sb += __shfl_xor_sync(0xffffffffu, sb, o);
        }
        const float ia = 1.f / sa, ib = 1.f / sb;
        #pragma unroll
        for (int j = 0; j < 8; j++) {
            sc[w][lane + j * 32]     = acc_a[j] * ia;
            sc[w + 8][lane + j * 32] = acc_b[j] * ib;
        }
    }
    __syncthreads();

    // ---- phase B: out[s][d] = sum_r p[s][r] * vp[d][r] ----
    const int d  = tid & 63;
    const int sq = tid >> 6;            // 0..3 -> rows sq*4 .. sq*4+3
    float oacc[4] = {0.f, 0.f, 0.f, 0.f};
    const float* vpb = g_vp + (size_t)bh * DK_ * R_;

    for (int rc = 0; rc < R_; rc += 64) {
        // load vp chunk [64 d][64 r] into buf with pad-65 rows
        #pragma unroll
        for (int u = 0; u < 4; u++) {
            int f   = tid + u * 256;
            int row = f >> 4;           // 0..63
            int c4  = (f & 15) * 4;
            float4 v = *(const float4*)(vpb + (size_t)row * R_ + rc + c4);
            buf[row * 65 + c4 + 0] = v.x; buf[row * 65 + c4 + 1] = v.y;
            buf[row * 65 + c4 + 2] = v.z; buf[row * 65 + c4 + 3] = v.w;
        }
        __syncthreads();
        #pragma unroll
        for (int rr = 0; rr < 64; rr++) {
            const float vv = buf[d * 65 + rr];
            #pragma unroll
            for (int i = 0; i < 4; i++)
                oacc[i] = fmaf(sc[sq * 4 + i][rc + rr], vv, oacc[i]);
        }
        __syncthreads();
    }

    #pragma unroll
    for (int i = 0; i < 4; i++) {
        const int s = s0 + sq * 4 + i;
        g_ao[(size_t)(b * S_ + s) * D_ + h * DK_ + d] = oacc[i];
    }
}

// ============================================================================
extern "C" void kernel_launch(void* const* d_in, const int* in_sizes, int n_in,
                              void* d_out, int out_size)
{
    const float* query = (const float*)d_in[0];
    const float* key   = (const float*)d_in[1];
    const float* value = (const float*)d_in[2];
    const float* Wq = (const float*)d_in[3];
    const float* bq = (const float*)d_in[4];
    const float* Wk = (const float*)d_in[5];
    const float* bk = (const float*)d_in[6];
    const float* Wv = (const float*)d_in[7];
    const float* bv = (const float*)d_in[8];
    const float* Wo = (const float*)d_in[9];
    const float* bo = (const float*)d_in[10];
    const float* E  = (const float*)d_in[11];
    const float* F  = (const float*)d_in[12];
    float* out = (float*)d_out;

    dim3 gg(D_ / 128, M_ / 128);
    gemm_nt<<<gg, 256>>>(query, Wq, bq, nullptr, 0);
    gemm_nt<<<gg, 256>>>(key,   Wk, bk, nullptr, 1);
    gemm_nt<<<gg, 256>>>(value, Wv, bv, nullptr, 2);
    proj_kernel<<<dim3(R_ / 128, 1, 2 * B_ * H_), 256>>>(E, F);
    attn_kernel<<<dim3(S_ / 16, B_ * H_), 256>>>();
    gemm_nt<<<gg, 256>>>(nullptr, Wo, bo, out, 3);
}

// round 4
// speedup vs baseline: 1.5560x; 1.5560x over previous
#include <cuda_runtime.h>
#include <cuda_bf16.h>
#include <math.h>
#include <stdint.h>

#define B_  4
#define S_  4096
#define D_  1024
#define H_  16
#define R_  256
#define DK_ 64
#define M_  (B_*S_)   // 16384 rows for the big GEMMs

// ---------------- scratch (device globals; no allocation allowed) ----------------
__device__ float g_q [B_*S_*D_];        // 64 MB
__device__ float g_k [B_*S_*D_];
__device__ float g_v [B_*S_*D_];
__device__ float g_ao[B_*S_*D_];        // attention output pre-Wo
__device__ float g_kp[B_*H_*DK_*R_];    // 16 MB
__device__ float g_vp[B_*H_*DK_*R_];

// split-bf16 staging (reused across the 4 GEMMs; stream-ordered)
__device__ __nv_bfloat16 g_ah[M_*D_];   // activation hi (32 MB)
__device__ __nv_bfloat16 g_al[M_*D_];   // activation lo
__device__ __nv_bfloat16 g_wh[D_*D_];   // weight hi (2 MB)
__device__ __nv_bfloat16 g_wl[D_*D_];   // weight lo

// ============================================================================
// helpers (baseline PTX only — plain sm_100 target, no tcgen05)
// ============================================================================
__device__ __forceinline__ uint32_t smem_u32(const void* p) {
    uint32_t a;
    asm("{ .reg .u64 t; cvta.to.shared.u64 t, %1; cvt.u32.u64 %0, t; }" : "=r"(a) : "l"(p));
    return a;
}
__device__ __forceinline__ void cp16(uint32_t dst, const void* src) {
    asm volatile("cp.async.cg.shared.global [%0], [%1], 16;" :: "r"(dst), "l"(src) : "memory");
}
__device__ __forceinline__ void cp_commit() {
    asm volatile("cp.async.commit_group;" ::: "memory");
}
template<int N> __device__ __forceinline__ void cp_wait() {
    asm volatile("cp.async.wait_group %0;" :: "n"(N) : "memory");
}
#define LDSM4(r, addr)                                                            \
    asm volatile("ldmatrix.sync.aligned.m8n8.x4.shared.b16 {%0,%1,%2,%3}, [%4];"  \
        : "=r"((r)[0]), "=r"((r)[1]), "=r"((r)[2]), "=r"((r)[3]) : "r"(addr))
#define MMA16816(d, a, b0, b1)                                                    \
    asm volatile("mma.sync.aligned.m16n8k16.row.col.f32.bf16.bf16.f32 "           \
        "{%0,%1,%2,%3}, {%4,%5,%6,%7}, {%8,%9}, {%0,%1,%2,%3};"                   \
        : "+f"((d)[0]), "+f"((d)[1]), "+f"((d)[2]), "+f"((d)[3])                  \
        : "r"((a)[0]), "r"((a)[1]), "r"((a)[2]), "r"((a)[3]), "r"(b0), "r"(b1))

// ============================================================================
// fp32 -> (hi, lo) bf16 split.  sel: 0 = activation (g_ah/g_al), 1 = weight.
// src == nullptr -> g_ao.
// ============================================================================
__global__ __launch_bounds__(256) void conv_kernel(const float* __restrict__ src,
                                                   int sel, int n4)
{
    const float* s = src ? src : g_ao;
    __nv_bfloat16* hi = (sel == 1) ? g_wh : g_ah;
    __nv_bfloat16* lo = (sel == 1) ? g_wl : g_al;
    int i = blockIdx.x * blockDim.x + threadIdx.x;
    if (i >= n4) return;
    float4 v = ((const float4*)s)[i];
    __nv_bfloat16 h[4], l[4];
    h[0] = __float2bfloat16(v.x); l[0] = __float2bfloat16(v.x - __bfloat162float(h[0]));
    h[1] = __float2bfloat16(v.y); l[1] = __float2bfloat16(v.y - __bfloat162float(h[1]));
    h[2] = __float2bfloat16(v.z); l[2] = __float2bfloat16(v.z - __bfloat162float(h[2]));
    h[3] = __float2bfloat16(v.w); l[3] = __float2bfloat16(v.w - __bfloat162float(h[3]));
    *(uint2*)(hi + 4 * (size_t)i) = *(uint2*)h;
    *(uint2*)(lo + 4 * (size_t)i) = *(uint2*)l;
}

// ============================================================================
// Split-bf16 HMMA GEMM: C[M,N] = A @ W^T + bias,  M=16384, N=K=1024.
// A = (g_ah, g_al), W = (g_wh, g_wl).
// CTA: 128x128x32, 256 threads (2x4 warps, 64x32 warp tile),
// cp.async 2-stage pipeline.  3 passes: Ah*Bh + Ah*Bl + Al*Bh (fp32 accum).
// smem rows: 32 bf16 + pad -> 80-byte stride (conflict-free ldmatrix).
// csel: 0->g_q, 1->g_k, 2->g_v, 3->Cext.
// ============================================================================
#define TILE_B   10240          // 128 rows * 80 bytes
#define STAGE_B  (4*TILE_B)     // AH, AL, BH, BL
#define GSMEM_B  (2*STAGE_B)    // 81920
#define NIT      (D_/32)        // 32 k-iterations

__device__ __forceinline__ void mm_issue(uint32_t sbase, int buf, int it,
                                         int m0, int n0, int tid)
{
    const int k0 = it * 32;
    const uint32_t sb = sbase + buf * STAGE_B;
    #pragma unroll
    for (int i = 0; i < 8; i++) {
        const int tile = i >> 1;                 // 0:AH 1:AL 2:BH 3:BL
        const int w    = tid + (i & 1) * 256;    // 0..511
        const int row  = w >> 2;                 // 0..127
        const int c16  = w & 3;                  // 16B chunk within 64B row
        const uint32_t dst = sb + tile * TILE_B + row * 80 + c16 * 16;
        const __nv_bfloat16* src;
        if (tile == 0)      src = g_ah + (size_t)(m0 + row) * D_ + k0 + c16 * 8;
        else if (tile == 1) src = g_al + (size_t)(m0 + row) * D_ + k0 + c16 * 8;
        else if (tile == 2) src = g_wh + (size_t)(n0 + row) * D_ + k0 + c16 * 8;
        else                src = g_wl + (size_t)(n0 + row) * D_ + k0 + c16 * 8;
        cp16(dst, src);
    }
    cp_commit();
}

__global__ __launch_bounds__(256, 2) void mm_gemm(const float* __restrict__ bias,
                                                  float* Cext, int csel)
{
    extern __shared__ char smem[];
    float* C = (csel == 0) ? g_q : (csel == 1) ? g_k : (csel == 2) ? g_v : Cext;

    const uint32_t sbase = smem_u32(smem);
    const int tid  = threadIdx.x;
    const int wid  = tid >> 5;
    const int lane = tid & 31;
    const int wm   = wid & 1;       // 2 warps along M
    const int wn   = wid >> 1;      // 4 warps along N
    const int m0   = blockIdx.y * 128;
    const int n0   = blockIdx.x * 128;

    float acc[4][4][4];
    #pragma unroll
    for (int mt = 0; mt < 4; mt++)
        #pragma unroll
        for (int nt = 0; nt < 4; nt++)
            #pragma unroll
            for (int e = 0; e < 4; e++) acc[mt][nt][e] = 0.f;

    const uint32_t lrow  = lane & 15;
    const uint32_t lhalf = (lane >> 4) * 16;

    mm_issue(sbase, 0, 0, m0, n0, tid);

    for (int it = 0; it < NIT; it++) {
        if (it + 1 < NIT) { mm_issue(sbase, (it + 1) & 1, it + 1, m0, n0, tid); cp_wait<1>(); }
        else              { cp_wait<0>(); }
        __syncthreads();

        const uint32_t sb = sbase + (it & 1) * STAGE_B;
        #pragma unroll
        for (int ks = 0; ks < 2; ks++) {
            const uint32_t koff = ks * 32;      // 16 bf16 = 32 bytes
            // B fragments (hi and lo), 2 groups of n16
            uint32_t bh[2][4], bl[2][4];
            #pragma unroll
            for (int ng = 0; ng < 2; ng++) {
                const uint32_t addr = sb + 2 * TILE_B
                    + (wn * 32 + ng * 16 + lrow) * 80 + koff + lhalf;
                LDSM4(bh[ng], addr);
                LDSM4(bl[ng], addr + TILE_B);
            }
            // A hi fragments
            uint32_t a[4][4];
            #pragma unroll
            for (int mt = 0; mt < 4; mt++) {
                const uint32_t addr = sb
                    + (wm * 64 + mt * 16 + lrow) * 80 + koff + lhalf;
                LDSM4(a[mt], addr);
            }
            // pass 1: Ah*Bh, pass 2: Ah*Bl
            #pragma unroll
            for (int mt = 0; mt < 4; mt++)
                #pragma unroll
                for (int nt = 0; nt < 4; nt++) {
                    const int ng = nt >> 1, hf = nt & 1;
                    MMA16816(acc[mt][nt], a[mt], bh[ng][hf], bh[ng][hf + 2]);
                    MMA16816(acc[mt][nt], a[mt], bl[ng][hf], bl[ng][hf + 2]);
                }
            // reload A lo into the same regs, pass 3: Al*Bh
            #pragma unroll
            for (int mt = 0; mt < 4; mt++) {
                const uint32_t addr = sb + TILE_B
                    + (wm * 64 + mt * 16 + lrow) * 80 + koff + lhalf;
                LDSM4(a[mt], addr);
            }
            #pragma unroll
            for (int mt = 0; mt < 4; mt++)
                #pragma unroll
                for (int nt = 0; nt < 4; nt++) {
                    const int ng = nt >> 1, hf = nt & 1;
                    MMA16816(acc[mt][nt], a[mt], bh[ng][hf], bh[ng][hf + 2]);
                }
        }
        __syncthreads();
    }

    // epilogue: C = acc + bias
    const int grp = lane >> 2;      // row within 8
    const int qp  = lane & 3;       // col pair
    #pragma unroll
    for (int mt = 0; mt < 4; mt++) {
        const int r0 = m0 + wm * 64 + mt * 16 + grp;
        #pragma unroll
        for (int nt = 0; nt < 4; nt++) {
            const int col = n0 + wn * 32 + nt * 8 + qp * 2;
            const float b0 = bias[col], b1 = bias[col + 1];
            *(float2*)(C + (size_t)r0 * D_ + col) =
                make_float2(acc[mt][nt][0] + b0, acc[mt][nt][1] + b1);
            *(float2*)(C + (size_t)(r0 + 8) * D_ + col) =
                make_float2(acc[mt][nt][2] + b0, acc[mt][nt][3] + b1);
        }
    }
}

// ============================================================================
// kp[b,h,d,r] = sum_s k[b,s,h*64+d] * E[h,s,r]    (and vp from v,F)  [unchanged]
// ============================================================================
__global__ __launch_bounds__(256) void proj_kernel(const float* __restrict__ E,
                                                   const float* __restrict__ F)
{
    const int z     = blockIdx.z;
    const int which = z >> 6;          // 0: kp, 1: vp
    const int bh    = z & 63;
    const int b     = bh >> 4, h = bh & 15;
    const float* Kin  = which ? g_v : g_k;
    const float* Ein  = which ? F : E;
    float*       Cout = which ? g_vp : g_kp;

    __shared__ float As[32][64];    // [s][d]
    __shared__ float Bs[32][128];   // [s][r]

    const int tid = threadIdx.x;
    const int r0  = blockIdx.x * 128;
    const int tx  = tid & 15;       // r-group (8 wide)
    const int ty  = tid >> 4;       // d-group (4 wide), 0..15

    float acc[4][8];
    #pragma unroll
    for (int i = 0; i < 4; i++)
        #pragma unroll
        for (int j = 0; j < 8; j++) acc[i][j] = 0.f;

    const float* Abase = Kin + (size_t)b * S_ * D_ + h * DK_;     // [s][d] stride D_
    const float* Bbase = Ein + (size_t)h * S_ * R_ + r0;          // [s][r] stride R_

    for (int s0 = 0; s0 < S_; s0 += 32) {
        #pragma unroll
        for (int u = 0; u < 2; u++) {            // A: 32x64 = 512 float4
            int f   = tid + u * 256;
            int row = f >> 4;                    // 0..31
            int c4  = (f & 15) * 4;
            *(float4*)&As[row][c4] =
                *(const float4*)(Abase + (size_t)(s0 + row) * D_ + c4);
        }
        #pragma unroll
        for (int u = 0; u < 4; u++) {            // B: 32x128 = 1024 float4
            int f   = tid + u * 256;
            int row = f >> 5;                    // 0..31
            int c4  = (f & 31) * 4;
            *(float4*)&Bs[row][c4] =
                *(const float4*)(Bbase + (size_t)(s0 + row) * R_ + c4);
        }
        __syncthreads();
        #pragma unroll
        for (int kk = 0; kk < 32; kk++) {
            float ra[4], rb[8];
            *(float4*)&ra[0] = *(const float4*)&As[kk][ty * 4];
            *(float4*)&rb[0] = *(const float4*)&Bs[kk][tx * 8];
            *(float4*)&rb[4] = *(const float4*)&Bs[kk][tx * 8 + 4];
            #pragma unroll
            for (int i = 0; i < 4; i++)
                #pragma unroll
                for (int j = 0; j < 8; j++)
                    acc[i][j] = fmaf(ra[i], rb[j], acc[i][j]);
        }
        __syncthreads();
    }

    float* Cb = Cout + (size_t)bh * DK_ * R_ + r0;
    #pragma unroll
    for (int i = 0; i < 4; i++) {
        const int d = ty * 4 + i;
        *(float4*)(Cb + (size_t)d * R_ + tx * 8) =
            make_float4(acc[i][0], acc[i][1], acc[i][2], acc[i][3]);
        *(float4*)(Cb + (size_t)d * R_ + tx * 8 + 4) =
            make_float4(acc[i][4], acc[i][5], acc[i][6], acc[i][7]);
    }
}

// ============================================================================
// Fused attention [unchanged]
// ============================================================================
__global__ __launch_bounds__(256) void attn_kernel()
{
    const int bh = blockIdx.y;
    const int b  = bh >> 4, h = bh & 15;
    const int s0 = blockIdx.x * 16;
    const int tid = threadIdx.x;

    __shared__ float qs[16][64];        // q tile, pre-scaled by 1/8
    __shared__ float sc[16][256];       // softmax probabilities
    __shared__ float buf[64 * 65];      // reused: kp chunk then vp chunk

    {
        int row = tid >> 4;             // 0..15
        int c4  = (tid & 15) * 4;
        float4 v = *(const float4*)(g_q + (size_t)(b * S_ + s0 + row) * D_ + h * DK_ + c4);
        qs[row][c4 + 0] = v.x * 0.125f; qs[row][c4 + 1] = v.y * 0.125f;
        qs[row][c4 + 2] = v.z * 0.125f; qs[row][c4 + 3] = v.w * 0.125f;
    }

    const int lane = tid & 31;
    const int w    = tid >> 5;          // 0..7
    float acc_a[8], acc_b[8];
    #pragma unroll
    for (int j = 0; j < 8; j++) { acc_a[j] = 0.f; acc_b[j] = 0.f; }

    const float* kpb = g_kp + (size_t)bh * DK_ * R_;
    for (int dc = 0; dc < DK_; dc += 16) {
        #pragma unroll
        for (int u = 0; u < 4; u++) {
            int f   = tid + u * 256;
            int row = f >> 6;           // 0..15
            int c4  = (f & 63) * 4;
            *(float4*)&buf[row * 256 + c4] =
                *(const float4*)(kpb + (size_t)(dc + row) * R_ + c4);
        }
        __syncthreads();
        #pragma unroll
        for (int dd = 0; dd < 16; dd++) {
            const float qa = qs[w][dc + dd];
            const float qb = qs[w + 8][dc + dd];
            #pragma unroll
            for (int j = 0; j < 8; j++) {
                const float bv = buf[dd * 256 + lane + j * 32];
                acc_a[j] = fmaf(qa, bv, acc_a[j]);
                acc_b[j] = fmaf(qb, bv, acc_b[j]);
            }
        }
        __syncthreads();
    }

    {
        float mxa = -1e30f, mxb = -1e30f;
        #pragma unroll
        for (int j = 0; j < 8; j++) { mxa = fmaxf(mxa, acc_a[j]); mxb = fmaxf(mxb, acc_b[j]); }
        #pragma unroll
        for (int o = 16; o > 0; o >>= 1) {
            mxa = fmaxf(mxa, __shfl_xor_sync(0xffffffffu, mxa, o));
            mxb = fmaxf(mxb, __shfl_xor_sync(0xffffffffu, mxb, o));
        }
        float sa = 0.f, sb = 0.f;
        #pragma unroll
        for (int j = 0; j < 8; j++) {
            acc_a[j] = __expf(acc_a[j] - mxa); sa += acc_a[j];
            acc_b[j] = __expf(acc_b[j] - mxb); sb += acc_b[j];
        }
        #pragma unroll
        for (int o = 16; o > 0; o >>= 1) {
            sa += __shfl_xor_sync(0xffffffffu, sa, o);
            sb += __shfl_xor_sync(0xffffffffu, sb, o);
        }
        const float ia = 1.f / sa, ib = 1.f / sb;
        #pragma unroll
        for (int j = 0; j < 8; j++) {
            sc[w][lane + j * 32]     = acc_a[j] * ia;
            sc[w + 8][lane + j * 32] = acc_b[j] * ib;
        }
    }
    __syncthreads();

    const int d  = tid & 63;
    const int sq = tid >> 6;            // 0..3
    float oacc[4] = {0.f, 0.f, 0.f, 0.f};
    const float* vpb = g_vp + (size_t)bh * DK_ * R_;

    for (int rc = 0; rc < R_; rc += 64) {
        #pragma unroll
        for (int u = 0; u < 4; u++) {
            int f   = tid + u * 256;
            int row = f >> 4;           // 0..63
            int c4  = (f & 15) * 4;
            float4 v = *(const float4*)(vpb + (size_t)row * R_ + rc + c4);
            buf[row * 65 + c4 + 0] = v.x; buf[row * 65 + c4 + 1] = v.y;
            buf[row * 65 + c4 + 2] = v.z; buf[row * 65 + c4 + 3] = v.w;
        }
        __syncthreads();
        #pragma unroll
        for (int rr = 0; rr < 64; rr++) {
            const float vv = buf[d * 65 + rr];
            #pragma unroll
            for (int i = 0; i < 4; i++)
                oacc[i] = fmaf(sc[sq * 4 + i][rc + rr], vv, oacc[i]);
        }
        __syncthreads();
    }

    #pragma unroll
    for (int i = 0; i < 4; i++) {
        const int s = s0 + sq * 4 + i;
        g_ao[(size_t)(b * S_ + s) * D_ + h * DK_ + d] = oacc[i];
    }
}

// ============================================================================
extern "C" void kernel_launch(void* const* d_in, const int* in_sizes, int n_in,
                              void* d_out, int out_size)
{
    const float* query = (const float*)d_in[0];
    const float* key   = (const float*)d_in[1];
    const float* value = (const float*)d_in[2];
    const float* Wq = (const float*)d_in[3];
    const float* bq = (const float*)d_in[4];
    const float* Wk = (const float*)d_in[5];
    const float* bk = (const float*)d_in[6];
    const float* Wv = (const float*)d_in[7];
    const float* bv = (const float*)d_in[8];
    const float* Wo = (const float*)d_in[9];
    const float* bo = (const float*)d_in[10];
    const float* E  = (const float*)d_in[11];
    const float* F  = (const float*)d_in[12];
    float* out = (float*)d_out;

    cudaFuncSetAttribute(mm_gemm, cudaFuncAttributeMaxDynamicSharedMemorySize, GSMEM_B);

    const int nA4 = M_ * D_ / 4;
    const int nW4 = D_ * D_ / 4;
    const dim3 gg(D_ / 128, M_ / 128);

    conv_kernel<<<nA4 / 256, 256>>>(query, 0, nA4);
    conv_kernel<<<nW4 / 256, 256>>>(Wq,    1, nW4);
    mm_gemm<<<gg, 256, GSMEM_B>>>(bq, nullptr, 0);

    conv_kernel<<<nA4 / 256, 256>>>(key, 0, nA4);
    conv_kernel<<<nW4 / 256, 256>>>(Wk,  1, nW4);
    mm_gemm<<<gg, 256, GSMEM_B>>>(bk, nullptr, 1);

    conv_kernel<<<nA4 / 256, 256>>>(value, 0, nA4);
    conv_kernel<<<nW4 / 256, 256>>>(Wv,    1, nW4);
    mm_gemm<<<gg, 256, GSMEM_B>>>(bv, nullptr, 2);

    proj_kernel<<<dim3(R_ / 128, 1, 2 * B_ * H_), 256>>>(E, F);
    attn_kernel<<<dim3(S_ / 16, B_ * H_), 256>>>();

    conv_kernel<<<nA4 / 256, 256>>>(nullptr, 0, nA4);   // g_ao
    conv_kernel<<<nW4 / 256, 256>>>(Wo,      1, nW4);
    mm_gemm<<<gg, 256, GSMEM_B>>>(bo, out, 3);
}

// round 5
// speedup vs baseline: 2.3694x; 1.5227x over previous
#include <cuda_runtime.h>
#include <cuda_bf16.h>
#include <math.h>
#include <stdint.h>

#define B_  4
#define S_  4096
#define D_  1024
#define H_  16
#define R_  256
#define DK_ 64
#define M_  (B_*S_)

// ---------------- scratch (device globals; no allocation allowed) ----------------
__device__ float g_ao[B_*S_*D_];                // attention output pre-Wo (fp32)

__device__ __nv_bfloat16 g_ah[M_*D_];           // gemm activation hi/lo staging
__device__ __nv_bfloat16 g_al[M_*D_];
__device__ __nv_bfloat16 g_wh[D_*D_];           // gemm weight hi/lo staging
__device__ __nv_bfloat16 g_wl[D_*D_];

__device__ __nv_bfloat16 g_qh[M_*D_], g_ql[M_*D_];   // q/k/v split (gemm epilogues)
__device__ __nv_bfloat16 g_kh[M_*D_], g_kl[M_*D_];
__device__ __nv_bfloat16 g_vh[M_*D_], g_vl[M_*D_];

__device__ __nv_bfloat16 g_eh[H_*S_*R_], g_el[H_*S_*R_];   // E/F split
__device__ __nv_bfloat16 g_fh[H_*S_*R_], g_fl[H_*S_*R_];

#define KPN (B_*H_*DK_*R_)
__device__ __nv_bfloat16 g_kph[KPN], g_kpl[KPN];     // kp/vp split (proj epilogue)
__device__ __nv_bfloat16 g_vph[KPN], g_vpl[KPN];

// ============================================================================
// helpers (baseline PTX only — plain sm_100 target)
// ============================================================================
__device__ __forceinline__ uint32_t smem_u32(const void* p) {
    uint32_t a;
    asm("{ .reg .u64 t; cvta.to.shared.u64 t, %1; cvt.u32.u64 %0, t; }" : "=r"(a) : "l"(p));
    return a;
}
__device__ __forceinline__ void cp16(uint32_t dst, const void* src) {
    asm volatile("cp.async.cg.shared.global [%0], [%1], 16;" :: "r"(dst), "l"(src) : "memory");
}
__device__ __forceinline__ void cp_commit() {
    asm volatile("cp.async.commit_group;" ::: "memory");
}
template<int N> __device__ __forceinline__ void cp_wait() {
    asm volatile("cp.async.wait_group %0;" :: "n"(N) : "memory");
}
#define LDSM4(r, addr)                                                            \
    asm volatile("ldmatrix.sync.aligned.m8n8.x4.shared.b16 {%0,%1,%2,%3}, [%4];"  \
        : "=r"((r)[0]), "=r"((r)[1]), "=r"((r)[2]), "=r"((r)[3]) : "r"(addr))
#define LDSM4T(r, addr)                                                                 \
    asm volatile("ldmatrix.sync.aligned.m8n8.x4.trans.shared.b16 {%0,%1,%2,%3}, [%4];"  \
        : "=r"((r)[0]), "=r"((r)[1]), "=r"((r)[2]), "=r"((r)[3]) : "r"(addr))
#define MMA16816(d, a, b0, b1)                                                    \
    asm volatile("mma.sync.aligned.m16n8k16.row.col.f32.bf16.bf16.f32 "           \
        "{%0,%1,%2,%3}, {%4,%5,%6,%7}, {%8,%9}, {%0,%1,%2,%3};"                   \
        : "+f"((d)[0]), "+f"((d)[1]), "+f"((d)[2]), "+f"((d)[3])                  \
        : "r"((a)[0]), "r"((a)[1]), "r"((a)[2]), "r"((a)[3]), "r"(b0), "r"(b1))

__device__ __forceinline__ uint32_t pack_bf2(float a, float b) {
    __nv_bfloat162 t = __floats2bfloat162_rn(a, b);
    return *(uint32_t*)&t;
}

// ============================================================================
// fp32 -> (hi, lo) bf16 split conversion.
// sel 0: (src ? src : g_ao) -> g_ah/g_al ; 1: W -> g_wh/g_wl ;
// sel 2: E -> g_eh/g_el     ; 3: F -> g_fh/g_fl
// ============================================================================
__global__ __launch_bounds__(256) void conv_kernel(const float* __restrict__ src,
                                                   int sel, int n4)
{
    const float* s;
    __nv_bfloat16 *hi, *lo;
    if (sel == 0)      { s = src ? src : g_ao; hi = g_ah; lo = g_al; }
    else if (sel == 1) { s = src; hi = g_wh; lo = g_wl; }
    else if (sel == 2) { s = src; hi = g_eh; lo = g_el; }
    else               { s = src; hi = g_fh; lo = g_fl; }
    int i = blockIdx.x * blockDim.x + threadIdx.x;
    if (i >= n4) return;
    float4 v = ((const float4*)s)[i];
    __nv_bfloat16 h[4], l[4];
    h[0] = __float2bfloat16(v.x); l[0] = __float2bfloat16(v.x - __bfloat162float(h[0]));
    h[1] = __float2bfloat16(v.y); l[1] = __float2bfloat16(v.y - __bfloat162float(h[1]));
    h[2] = __float2bfloat16(v.z); l[2] = __float2bfloat16(v.z - __bfloat162float(h[2]));
    h[3] = __float2bfloat16(v.w); l[3] = __float2bfloat16(v.w - __bfloat162float(h[3]));
    *(uint2*)(hi + 4 * (size_t)i) = *(uint2*)h;
    *(uint2*)(lo + 4 * (size_t)i) = *(uint2*)l;
}

// ============================================================================
// Split-bf16 HMMA GEMM: C = A @ W^T + bias. 128x128x32 CTA, 3-pass split.
// csel 0/1/2 -> write split bf16 (qh/ql, kh/kl, vh/vl); csel 3 -> fp32 Cext.
// ============================================================================
#define TILE_B   10240
#define STAGE_B  (4*TILE_B)
#define GSMEM_B  (2*STAGE_B)
#define NIT      (D_/32)

__device__ __forceinline__ void mm_issue(uint32_t sbase, int buf, int it,
                                         int m0, int n0, int tid)
{
    const int k0 = it * 32;
    const uint32_t sb = sbase + buf * STAGE_B;
    #pragma unroll
    for (int i = 0; i < 8; i++) {
        const int tile = i >> 1;
        const int w    = tid + (i & 1) * 256;
        const int row  = w >> 2;
        const int c16  = w & 3;
        const uint32_t dst = sb + tile * TILE_B + row * 80 + c16 * 16;
        const __nv_bfloat16* src;
        if (tile == 0)      src = g_ah + (size_t)(m0 + row) * D_ + k0 + c16 * 8;
        else if (tile == 1) src = g_al + (size_t)(m0 + row) * D_ + k0 + c16 * 8;
        else if (tile == 2) src = g_wh + (size_t)(n0 + row) * D_ + k0 + c16 * 8;
        else                src = g_wl + (size_t)(n0 + row) * D_ + k0 + c16 * 8;
        cp16(dst, src);
    }
    cp_commit();
}

__global__ __launch_bounds__(256, 2) void mm_gemm(const float* __restrict__ bias,
                                                  float* Cext, int csel)
{
    extern __shared__ char smem[];
    const uint32_t sbase = smem_u32(smem);
    const int tid  = threadIdx.x;
    const int wid  = tid >> 5;
    const int lane = tid & 31;
    const int wm   = wid & 1;
    const int wn   = wid >> 1;
    const int m0   = blockIdx.y * 128;
    const int n0   = blockIdx.x * 128;

    float acc[4][4][4];
    #pragma unroll
    for (int mt = 0; mt < 4; mt++)
        #pragma unroll
        for (int nt = 0; nt < 4; nt++)
            #pragma unroll
            for (int e = 0; e < 4; e++) acc[mt][nt][e] = 0.f;

    const uint32_t lrow  = lane & 15;
    const uint32_t lhalf = (lane >> 4) * 16;

    mm_issue(sbase, 0, 0, m0, n0, tid);

    for (int it = 0; it < NIT; it++) {
        if (it + 1 < NIT) { mm_issue(sbase, (it + 1) & 1, it + 1, m0, n0, tid); cp_wait<1>(); }
        else              { cp_wait<0>(); }
        __syncthreads();

        const uint32_t sb = sbase + (it & 1) * STAGE_B;
        #pragma unroll
        for (int ks = 0; ks < 2; ks++) {
            const uint32_t koff = ks * 32;
            uint32_t bh[2][4], bl[2][4];
            #pragma unroll
            for (int ng = 0; ng < 2; ng++) {
                const uint32_t addr = sb + 2 * TILE_B
                    + (wn * 32 + ng * 16 + lrow) * 80 + koff + lhalf;
                LDSM4(bh[ng], addr);
                LDSM4(bl[ng], addr + TILE_B);
            }
            uint32_t a[4][4];
            #pragma unroll
            for (int mt = 0; mt < 4; mt++) {
                const uint32_t addr = sb
                    + (wm * 64 + mt * 16 + lrow) * 80 + koff + lhalf;
                LDSM4(a[mt], addr);
            }
            #pragma unroll
            for (int mt = 0; mt < 4; mt++)
                #pragma unroll
                for (int nt = 0; nt < 4; nt++) {
                    const int ng = nt >> 1, hf = nt & 1;
                    MMA16816(acc[mt][nt], a[mt], bh[ng][hf], bh[ng][hf + 2]);
                    MMA16816(acc[mt][nt], a[mt], bl[ng][hf], bl[ng][hf + 2]);
                }
            #pragma unroll
            for (int mt = 0; mt < 4; mt++) {
                const uint32_t addr = sb + TILE_B
                    + (wm * 64 + mt * 16 + lrow) * 80 + koff + lhalf;
                LDSM4(a[mt], addr);
            }
            #pragma unroll
            for (int mt = 0; mt < 4; mt++)
                #pragma unroll
                for (int nt = 0; nt < 4; nt++) {
                    const int ng = nt >> 1, hf = nt & 1;
                    MMA16816(acc[mt][nt], a[mt], bh[ng][hf], bh[ng][hf + 2]);
                }
        }
        __syncthreads();
    }

    const int grp = lane >> 2;
    const int qp  = lane & 3;
    if (csel < 3) {
        __nv_bfloat16 *OH, *OL;
        if (csel == 0)      { OH = g_qh; OL = g_ql; }
        else if (csel == 1) { OH = g_kh; OL = g_kl; }
        else                { OH = g_vh; OL = g_vl; }
        #pragma unroll
        for (int mt = 0; mt < 4; mt++) {
            const int r0 = m0 + wm * 64 + mt * 16 + grp;
            #pragma unroll
            for (int nt = 0; nt < 4; nt++) {
                const int col = n0 + wn * 32 + nt * 8 + qp * 2;
                const float b0 = bias[col], b1 = bias[col + 1];
                float v0 = acc[mt][nt][0] + b0, v1 = acc[mt][nt][1] + b1;
                float v2 = acc[mt][nt][2] + b0, v3 = acc[mt][nt][3] + b1;
                float h0 = __bfloat162float(__float2bfloat16(v0));
                float h1 = __bfloat162float(__float2bfloat16(v1));
                float h2 = __bfloat162float(__float2bfloat16(v2));
                float h3 = __bfloat162float(__float2bfloat16(v3));
                *(uint32_t*)(OH + (size_t)r0 * D_ + col)       = pack_bf2(v0, v1);
                *(uint32_t*)(OL + (size_t)r0 * D_ + col)       = pack_bf2(v0 - h0, v1 - h1);
                *(uint32_t*)(OH + (size_t)(r0 + 8) * D_ + col) = pack_bf2(v2, v3);
                *(uint32_t*)(OL + (size_t)(r0 + 8) * D_ + col) = pack_bf2(v2 - h2, v3 - h3);
            }
        }
    } else {
        #pragma unroll
        for (int mt = 0; mt < 4; mt++) {
            const int r0 = m0 + wm * 64 + mt * 16 + grp;
            #pragma unroll
            for (int nt = 0; nt < 4; nt++) {
                const int col = n0 + wn * 32 + nt * 8 + qp * 2;
                const float b0 = bias[col], b1 = bias[col + 1];
                *(float2*)(Cext + (size_t)r0 * D_ + col) =
                    make_float2(acc[mt][nt][0] + b0, acc[mt][nt][1] + b1);
                *(float2*)(Cext + (size_t)(r0 + 8) * D_ + col) =
                    make_float2(acc[mt][nt][2] + b0, acc[mt][nt][3] + b1);
            }
        }
    }
}

// ============================================================================
// proj (HMMA): kp[bh][d][r] = sum_s k[b][s][hd] * E[h][s][r]  (split 3-pass)
// One CTA per (which,bh): grid.x = 128.  C = 64(d) x 256(r), K = S = 4096.
// A via ldsm.trans from k tiles [s][d]; B via ldsm.trans from E tiles [s][r].
// 8 warps, each 64(d) x 32(r).  Epilogue stores split bf16 kp/vp.
// ============================================================================
#define PJ_KH 0
#define PJ_KL 4608
#define PJ_EH 9216
#define PJ_EL 26112
#define PJ_STAGE 43008
#define PJ_SMEM  (2*PJ_STAGE)

__global__ __launch_bounds__(256, 1) void proj_mma()
{
    extern __shared__ char sm[];
    const uint32_t sb = smem_u32(sm);
    const int bx = blockIdx.x;
    const int which = bx >> 6, bh = bx & 63;
    const int b = bh >> 4, h = bh & 15;
    const __nv_bfloat16* Ah = which ? g_vh : g_kh;
    const __nv_bfloat16* Al = which ? g_vl : g_kl;
    const __nv_bfloat16* Eh = which ? g_fh : g_eh;
    const __nv_bfloat16* El = which ? g_fl : g_el;
    __nv_bfloat16* Oh = which ? g_vph : g_kph;
    __nv_bfloat16* Ol = which ? g_vpl : g_kpl;

    const int tid = threadIdx.x, wid = tid >> 5, lane = tid & 31;
    const int wn = wid;             // 8 warps * 32 r

    float acc[4][4][4];
    #pragma unroll
    for (int mt = 0; mt < 4; mt++)
        #pragma unroll
        for (int nt = 0; nt < 4; nt++)
            #pragma unroll
            for (int e = 0; e < 4; e++) acc[mt][nt][e] = 0.f;

    // producer lambda-ish: issue one stage
    auto issue = [&](int buf, int it) {
        const int s0 = it * 32;
        const uint32_t st = sb + buf * PJ_STAGE;
        #pragma unroll
        for (int i = 0; i < 10; i++) {
            const int c = tid + i * 256;      // 0..2559
            uint32_t dst; const __nv_bfloat16* src;
            if (c < 512) {
                const int sp = c >> 8, idx = c & 255, row = idx >> 3, ch = idx & 7;
                dst = st + (sp ? PJ_KL : PJ_KH) + row * 144 + ch * 16;
                src = (sp ? Al : Ah) + ((size_t)(b * S_ + s0 + row) * D_ + h * DK_ + ch * 8);
            } else {
                const int i2 = c - 512, sp = i2 >> 10, idx = i2 & 1023;
                const int row = idx >> 5, ch = idx & 31;
                dst = st + (sp ? PJ_EL : PJ_EH) + row * 528 + ch * 16;
                src = (sp ? El : Eh) + ((size_t)(h * S_ + s0 + row) * R_ + ch * 8);
            }
            cp16(dst, src);
        }
        cp_commit();
    };

    issue(0, 0);
    const uint32_t arow = (lane & 7) + ((lane >> 4) << 3);     // A trans row
    const uint32_t acol = ((lane >> 3) & 1) * 16;              // A trans col bytes
    const uint32_t brow = lane & 15;
    const uint32_t bcol = (lane >> 4) * 16;

    for (int it = 0; it < 128; it++) {
        if (it + 1 < 128) { issue((it + 1) & 1, it + 1); cp_wait<1>(); }
        else              { cp_wait<0>(); }
        __syncthreads();
        const uint32_t st = sb + (it & 1) * PJ_STAGE;
        #pragma unroll
        for (int ks = 0; ks < 2; ks++) {
            uint32_t ah[4][4], al[4][4];
            #pragma unroll
            for (int mt = 0; mt < 4; mt++) {
                const uint32_t addr = st + PJ_KH
                    + (ks * 16 + arow) * 144 + mt * 32 + acol;
                LDSM4T(ah[mt], addr);
                LDSM4T(al[mt], addr + (PJ_KL - PJ_KH));
            }
            #pragma unroll
            for (int bb = 0; bb < 2; bb++) {
                uint32_t bhh[4], bll[4];
                const uint32_t addr = st + PJ_EH
                    + (ks * 16 + brow) * 528 + (wn * 32 + bb * 16) * 2 + bcol;
                LDSM4T(bhh, addr);
                LDSM4T(bll, addr + (PJ_EL - PJ_EH));
                #pragma unroll
                for (int mt = 0; mt < 4; mt++) {
                    MMA16816(acc[mt][bb*2],   ah[mt], bhh[0], bhh[1]);
                    MMA16816(acc[mt][bb*2+1], ah[mt], bhh[2], bhh[3]);
                    MMA16816(acc[mt][bb*2],   ah[mt], bll[0], bll[1]);
                    MMA16816(acc[mt][bb*2+1], ah[mt], bll[2], bll[3]);
                    MMA16816(acc[mt][bb*2],   al[mt], bhh[0], bhh[1]);
                    MMA16816(acc[mt][bb*2+1], al[mt], bhh[2], bhh[3]);
                }
            }
        }
        __syncthreads();
    }

    // epilogue: split-bf16 store of kp/vp [bh][d][R]
    const int grp = lane >> 2, qp = lane & 3;
    #pragma unroll
    for (int mt = 0; mt < 4; mt++) {
        #pragma unroll
        for (int nt = 0; nt < 4; nt++) {
            const int d0 = mt * 16 + grp;
            const int r  = wn * 32 + nt * 8 + qp * 2;
            const size_t i0 = (size_t)bh * DK_ * R_ + (size_t)d0 * R_ + r;
            const size_t i1 = i0 + 8 * R_;
            float v0 = acc[mt][nt][0], v1 = acc[mt][nt][1];
            float v2 = acc[mt][nt][2], v3 = acc[mt][nt][3];
            float h0 = __bfloat162float(__float2bfloat16(v0));
            float h1 = __bfloat162float(__float2bfloat16(v1));
            float h2 = __bfloat162float(__float2bfloat16(v2));
            float h3 = __bfloat162float(__float2bfloat16(v3));
            *(uint32_t*)(Oh + i0) = pack_bf2(v0, v1);
            *(uint32_t*)(Ol + i0) = pack_bf2(v0 - h0, v1 - h1);
            *(uint32_t*)(Oh + i1) = pack_bf2(v2, v3);
            *(uint32_t*)(Ol + i1) = pack_bf2(v2 - h2, v3 - h3);
        }
    }
}

// ============================================================================
// attention (HMMA): per block 64 s-rows x one (b,h).
// Phase A: scores = split-q x split-kp (3-pass), softmax in frag layout,
// p split to bf16 hi/lo in registers, Phase B: out = 3-pass p x vp.
// 8 warps: wm = wid&3 (m16 rows), wn = wid>>2 (r-half 128).
// ============================================================================
#define AT_QH   0
#define AT_QL   9216
#define AT_KPH  18432
#define AT_KPL  52224
#define AT_VPH  86016
#define AT_VPL  119808
#define AT_OUT  153600
#define AT_RED0 170496
#define AT_RED1 171008
#define AT_SMEM 171520

__global__ __launch_bounds__(256, 1) void attn_mma()
{
    extern __shared__ char sm[];
    const uint32_t sb = smem_u32(sm);
    const int bh = blockIdx.y, b = bh >> 4, h = bh & 15;
    const int s0 = blockIdx.x * 64;
    const int tid = threadIdx.x, wid = tid >> 5, lane = tid & 31;
    const int wm = wid & 3, wn = wid >> 2;

    // ---- load everything (q, kp, vp split) ----
    #pragma unroll
    for (int i = 0; i < 36; i++) {
        const int c = tid + i * 256;       // 0..9215
        uint32_t dst; const __nv_bfloat16* src;
        if (c < 1024) {
            const int sp = c >> 9, idx = c & 511, row = idx >> 3, ch = idx & 7;
            dst = sb + (sp ? AT_QL : AT_QH) + row * 144 + ch * 16;
            src = (sp ? g_ql : g_qh) + ((size_t)(b * S_ + s0 + row) * D_ + h * DK_ + ch * 8);
        } else if (c < 5120) {
            const int i2 = c - 1024, sp = i2 >> 11, idx = i2 & 2047;
            const int row = idx >> 5, ch = idx & 31;
            dst = sb + (sp ? AT_KPL : AT_KPH) + row * 528 + ch * 16;
            src = (sp ? g_kpl : g_kph) + ((size_t)bh * DK_ * R_ + row * R_ + ch * 8);
        } else {
            const int i2 = c - 5120, sp = i2 >> 11, idx = i2 & 2047;
            const int row = idx >> 5, ch = idx & 31;
            dst = sb + (sp ? AT_VPL : AT_VPH) + row * 528 + ch * 16;
            src = (sp ? g_vpl : g_vph) + ((size_t)bh * DK_ * R_ + row * R_ + ch * 8);
        }
        cp16(dst, src);
    }
    cp_commit(); cp_wait<0>();
    __syncthreads();

    // ---- phase A: scores (16 s x 128 r per warp) ----
    float acc[16][4];
    #pragma unroll
    for (int j = 0; j < 16; j++)
        #pragma unroll
        for (int e = 0; e < 4; e++) acc[j][e] = 0.f;

    #pragma unroll
    for (int kd = 0; kd < 4; kd++) {
        uint32_t ah[4], al[4];
        const uint32_t qaddr = sb + AT_QH
            + (wm * 16 + (lane & 15)) * 144 + kd * 32 + (lane >> 4) * 16;
        LDSM4(ah, qaddr);
        LDSM4(al, qaddr + (AT_QL - AT_QH));
        #pragma unroll
        for (int bb = 0; bb < 8; bb++) {
            uint32_t bhh[4], bll[4];
            const uint32_t baddr = sb + AT_KPH
                + (kd * 16 + (lane & 15)) * 528 + (wn * 128 + bb * 16) * 2 + (lane >> 4) * 16;
            LDSM4T(bhh, baddr);
            LDSM4T(bll, baddr + (AT_KPL - AT_KPH));
            MMA16816(acc[bb*2],   ah, bhh[0], bhh[1]);
            MMA16816(acc[bb*2+1], ah, bhh[2], bhh[3]);
            MMA16816(acc[bb*2],   ah, bll[0], bll[1]);
            MMA16816(acc[bb*2+1], ah, bll[2], bll[3]);
            MMA16816(acc[bb*2],   al, bhh[0], bhh[1]);
            MMA16816(acc[bb*2+1], al, bhh[2], bhh[3]);
        }
    }

    // ---- softmax (rows: wm*16 + lane>>2 and +8; each warp holds 128 of 256 r) ----
    float* red0 = (float*)(sm + AT_RED0);
    float* red1 = (float*)(sm + AT_RED1);
    const int row0 = wm * 16 + (lane >> 2);
    const int row1 = row0 + 8;

    float mx0 = -1e30f, mx1 = -1e30f;
    #pragma unroll
    for (int j = 0; j < 16; j++) {
        mx0 = fmaxf(mx0, fmaxf(acc[j][0], acc[j][1]));
        mx1 = fmaxf(mx1, fmaxf(acc[j][2], acc[j][3]));
    }
    mx0 = fmaxf(mx0, __shfl_xor_sync(0xffffffffu, mx0, 1));
    mx0 = fmaxf(mx0, __shfl_xor_sync(0xffffffffu, mx0, 2));
    mx1 = fmaxf(mx1, __shfl_xor_sync(0xffffffffu, mx1, 1));
    mx1 = fmaxf(mx1, __shfl_xor_sync(0xffffffffu, mx1, 2));
    if ((lane & 3) == 0) { red0[row0 * 2 + wn] = mx0; red0[row1 * 2 + wn] = mx1; }
    __syncthreads();
    const float m0 = fmaxf(red0[row0 * 2], red0[row0 * 2 + 1]);
    const float m1 = fmaxf(red0[row1 * 2], red0[row1 * 2 + 1]);

    float su0 = 0.f, su1 = 0.f;
    #pragma unroll
    for (int j = 0; j < 16; j++) {
        acc[j][0] = __expf((acc[j][0] - m0) * 0.125f);
        acc[j][1] = __expf((acc[j][1] - m0) * 0.125f);
        acc[j][2] = __expf((acc[j][2] - m1) * 0.125f);
        acc[j][3] = __expf((acc[j][3] - m1) * 0.125f);
        su0 += acc[j][0] + acc[j][1];
        su1 += acc[j][2] + acc[j][3];
    }
    su0 += __shfl_xor_sync(0xffffffffu, su0, 1);
    su0 += __shfl_xor_sync(0xffffffffu, su0, 2);
    su1 += __shfl_xor_sync(0xffffffffu, su1, 1);
    su1 += __shfl_xor_sync(0xffffffffu, su1, 2);
    if ((lane & 3) == 0) { red1[row0 * 2 + wn] = su0; red1[row1 * 2 + wn] = su1; }
    __syncthreads();
    const float inv0 = 1.f / (red1[row0 * 2] + red1[row0 * 2 + 1]);
    const float inv1 = 1.f / (red1[row1 * 2] + red1[row1 * 2 + 1]);

    // p = normalized probs, split to bf16 hi/lo (in accum == A-frag layout)
    uint32_t ph[16][2], pl[16][2];
    #pragma unroll
    for (int j = 0; j < 16; j++) {
        const float p0 = acc[j][0] * inv0, p1 = acc[j][1] * inv0;
        const float p2 = acc[j][2] * inv1, p3 = acc[j][3] * inv1;
        const float h0 = __bfloat162float(__float2bfloat16(p0));
        const float h1 = __bfloat162float(__float2bfloat16(p1));
        const float h2 = __bfloat162float(__float2bfloat16(p2));
        const float h3 = __bfloat162float(__float2bfloat16(p3));
        ph[j][0] = pack_bf2(p0, p1);       ph[j][1] = pack_bf2(p2, p3);
        pl[j][0] = pack_bf2(p0 - h0, p1 - h1);
        pl[j][1] = pack_bf2(p2 - h2, p3 - h3);
    }

    // ---- phase B: out += p @ vp^T over this warp's r-half (k-partial) ----
    float acc2[8][4];
    #pragma unroll
    for (int nn = 0; nn < 8; nn++)
        #pragma unroll
        for (int e = 0; e < 4; e++) acc2[nn][e] = 0.f;

    #pragma unroll
    for (int jj = 0; jj < 8; jj++) {
        uint32_t a_h[4] = { ph[2*jj][0], ph[2*jj][1], ph[2*jj+1][0], ph[2*jj+1][1] };
        uint32_t a_l[4] = { pl[2*jj][0], pl[2*jj][1], pl[2*jj+1][0], pl[2*jj+1][1] };
        #pragma unroll
        for (int nb = 0; nb < 4; nb++) {
            uint32_t bhh[4], bll[4];
            const uint32_t baddr = sb + AT_VPH
                + (nb * 16 + (lane & 15)) * 528 + (wn * 128 + jj * 16) * 2 + (lane >> 4) * 16;
            LDSM4(bhh, baddr);
            LDSM4(bll, baddr + (AT_VPL - AT_VPH));
            MMA16816(acc2[nb*2],   a_h, bhh[0], bhh[2]);
            MMA16816(acc2[nb*2+1], a_h, bhh[1], bhh[3]);
            MMA16816(acc2[nb*2],   a_h, bll[0], bll[2]);
            MMA16816(acc2[nb*2+1], a_h, bll[1], bll[3]);
            MMA16816(acc2[nb*2],   a_l, bhh[0], bhh[2]);
            MMA16816(acc2[nb*2+1], a_l, bhh[1], bhh[3]);
        }
    }

    // ---- combine the two r-half partials and write g_ao ----
    float* outb = (float*)(sm + AT_OUT);
    const int qp = lane & 3;
    __syncthreads();
    if (wn == 1) {
        #pragma unroll
        for (int nn = 0; nn < 8; nn++) {
            const int c = nn * 8 + qp * 2;
            outb[row0 * 66 + c] = acc2[nn][0]; outb[row0 * 66 + c + 1] = acc2[nn][1];
            outb[row1 * 66 + c] = acc2[nn][2]; outb[row1 * 66 + c + 1] = acc2[nn][3];
        }
    }
    __syncthreads();
    if (wn == 0) {
        #pragma unroll
        for (int nn = 0; nn < 8; nn++) {
            const int c = nn * 8 + qp * 2;
            const float v0 = acc2[nn][0] + outb[row0 * 66 + c];
            const float v1 = acc2[nn][1] + outb[row0 * 66 + c + 1];
            const float v2 = acc2[nn][2] + outb[row1 * 66 + c];
            const float v3 = acc2[nn][3] + outb[row1 * 66 + c + 1];
            *(float2*)(g_ao + (size_t)(b * S_ + s0 + row0) * D_ + h * DK_ + c) =
                make_float2(v0, v1);
            *(float2*)(g_ao + (size_t)(b * S_ + s0 + row1) * D_ + h * DK_ + c) =
                make_float2(v2, v3);
        }
    }
}

// ============================================================================
extern "C" void kernel_launch(void* const* d_in, const int* in_sizes, int n_in,
                              void* d_out, int out_size)
{
    const float* query = (const float*)d_in[0];
    const float* key   = (const float*)d_in[1];
    const float* value = (const float*)d_in[2];
    const float* Wq = (const float*)d_in[3];
    const float* bq = (const float*)d_in[4];
    const float* Wk = (const float*)d_in[5];
    const float* bk = (const float*)d_in[6];
    const float* Wv = (const float*)d_in[7];
    const float* bv = (const float*)d_in[8];
    const float* Wo = (const float*)d_in[9];
    const float* bo = (const float*)d_in[10];
    const float* E  = (const float*)d_in[11];
    const float* F  = (const float*)d_in[12];
    float* out = (float*)d_out;

    cudaFuncSetAttribute(mm_gemm,  cudaFuncAttributeMaxDynamicSharedMemorySize, GSMEM_B);
    cudaFuncSetAttribute(proj_mma, cudaFuncAttributeMaxDynamicSharedMemorySize, PJ_SMEM);
    cudaFuncSetAttribute(attn_mma, cudaFuncAttributeMaxDynamicSharedMemorySize, AT_SMEM);

    const int nA4 = M_ * D_ / 4;
    const int nW4 = D_ * D_ / 4;
    const int nE4 = H_ * S_ * R_ / 4;
    const dim3 gg(D_ / 128, M_ / 128);

    conv_kernel<<<nA4 / 256, 256>>>(query, 0, nA4);
    conv_kernel<<<nW4 / 256, 256>>>(Wq,    1, nW4);
    mm_gemm<<<gg, 256, GSMEM_B>>>(bq, nullptr, 0);

    conv_kernel<<<nA4 / 256, 256>>>(key, 0, nA4);
    conv_kernel<<<nW4 / 256, 256>>>(Wk,  1, nW4);
    mm_gemm<<<gg, 256, GSMEM_B>>>(bk, nullptr, 1);

    conv_kernel<<<nA4 / 256, 256>>>(value, 0, nA4);
    conv_kernel<<<nW4 / 256, 256>>>(Wv,    1, nW4);
    mm_gemm<<<gg, 256, GSMEM_B>>>(bv, nullptr, 2);

    conv_kernel<<<nE4 / 256, 256>>>(E, 2, nE4);
    conv_kernel<<<nE4 / 256, 256>>>(F, 3, nE4);

    proj_mma<<<128, 256, PJ_SMEM>>>();
    attn_mma<<<dim3(64, 64), 256, AT_SMEM>>>();

    conv_kernel<<<nA4 / 256, 256>>>(nullptr, 0, nA4);
    conv_kernel<<<nW4 / 256, 256>>>(Wo,      1, nW4);
    mm_gemm<<<gg, 256, GSMEM_B>>>(bo, out, 3);
}